// round 6
// baseline (speedup 1.0000x reference)
#include <cuda_runtime.h>
#include <cuda_bf16.h>
#include <cstdint>

#define NB 2
#define NC 256
#define HW 2304   // 48*48
#define WD 48

// ---------------- device scratch ----------------
__device__ float g_q[NB * NC * HW];
__device__ float g_k[NB * NC * HW];
__device__ float g_v[NB * NC * HW];

__device__ __forceinline__ uint32_t smem_u32(const void* p) {
    uint32_t a;
    asm("{ .reg .u64 t; cvta.to.shared.u64 t, %1; cvt.u32.u64 %0, t; }"
        : "=r"(a) : "l"(p));
    return a;
}
__device__ __forceinline__ uint32_t pack_hi(__nv_bfloat16 a, __nv_bfloat16 b) {
    return ((uint32_t)*(uint16_t*)&b << 16) | *(uint16_t*)&a;
}
__device__ __forceinline__ uint32_t pack_bf16(float a, float b) {
    __nv_bfloat162 h = __floats2bfloat162_rn(a, b);
    return *(uint32_t*)&h;
}

// ---------------------------------------------------------------------------
// Hybrid GEMM: D[oc,pix] = sum_c W[oc,c] * X[c,pix]  (M=768, N=4608, K=256)
// oc-tile r = blockIdx.x % 12:
//   r < 5  -> TENSOR path: bf16 hi/lo 3-pass mma.sync (oc 0..319)
//   r >= 5 -> SIMT  path: fp32 FFMA, exact       (oc 320..767)
// Both tile 64oc x 128pix. Paths use different HW pipes and co-reside.
// Tensor fill reads fp32 x/w directly: transpose + bf16 split in flight
// (no prep kernel, no intermediate arrays).
// grid 432, block 256, smem 55296.
// ---------------------------------------------------------------------------
#define A_TILE_B 9216              // 64 * 144
#define B_TILE_B 18432             // 128 * 144
#define GEMM_SMEM (2 * A_TILE_B + 2 * B_TILE_B)   // 55296

__device__ __forceinline__ void mma_bf16(float* d, const uint32_t* a,
                                         const uint32_t* b) {
    asm volatile(
        "mma.sync.aligned.m16n8k16.row.col.f32.bf16.bf16.f32 "
        "{%0,%1,%2,%3}, {%4,%5,%6,%7}, {%8,%9}, {%0,%1,%2,%3};"
        : "+f"(d[0]), "+f"(d[1]), "+f"(d[2]), "+f"(d[3])
        : "r"(a[0]), "r"(a[1]), "r"(a[2]), "r"(a[3]), "r"(b[0]), "r"(b[1]));
}

__global__ __launch_bounds__(256, 3) void gemm_hybrid(
    const float* __restrict__ x, const float* __restrict__ wq,
    const float* __restrict__ wk, const float* __restrict__ wv)
{
    extern __shared__ char sm[];

    int gb  = blockIdx.x;
    int r   = gb % 12;            // oc tile 0..11
    int pt  = gb / 12;            // pix tile 0..35
    int N0  = pt * 128;           // global pixel base
    int oc0 = r * 64;             // global oc base
    int which = oc0 >> 8;
    int ol    = oc0 & 255;
    const float* w   = (which == 0) ? wq : (which == 1) ? wk : wv;
    float*      obuf = (which == 0) ? g_q : (which == 1) ? g_k : g_v;

    int b   = N0 / HW;
    int pl0 = N0 - b * HW;        // local pixel base within batch
    const float* xb = x + (size_t)b * NC * HW;
    float* ob = obuf + (size_t)b * NC * HW;

    int tid = threadIdx.x;

    if (r < 5) {
        // =================== TENSOR PATH ===================
        uint32_t uS = smem_u32(sm);
        int l   = tid & 31;
        int wid = tid >> 5;
        int wm  = wid >> 2;       // 0..1, 32 oc each
        int wn  = wid & 3;        // 0..3, 32 pix each

        float acc[2][4][4];
        #pragma unroll
        for (int i = 0; i < 2; i++)
            #pragma unroll
            for (int j = 0; j < 4; j++)
                #pragma unroll
                for (int q = 0; q < 4; q++) acc[i][j][q] = 0.f;

        uint32_t aLane = (uint32_t)((wm * 32 + (l & 15)) * 144 + (l >> 4) * 16);
        uint32_t bLane = (uint32_t)((wn * 32 + ((l >> 4) & 1) * 8 + (l & 7)) * 144
                                    + ((l >> 3) & 1) * 16);
        const int selA[3] = {0, 0, 1};
        const int selB[3] = {0, 1, 0};

        for (int kt = 0; kt < 4; kt++) {
            __syncthreads();
            // --- A fill: W[ol..ol+63][kt*64..+63] fp32 -> bf16 hi/lo ---
            #pragma unroll
            for (int it = 0; it < 4; it++) {
                int t  = it * 256 + tid;
                int oc = t >> 4;
                int cg = t & 15;
                float4 v = *(const float4*)(w + (size_t)(ol + oc) * 256
                                            + kt * 64 + cg * 4);
                __nv_bfloat16 h0 = __float2bfloat16(v.x);
                __nv_bfloat16 h1 = __float2bfloat16(v.y);
                __nv_bfloat16 h2 = __float2bfloat16(v.z);
                __nv_bfloat16 h3 = __float2bfloat16(v.w);
                uint2 hi, lo;
                hi.x = pack_hi(h0, h1);
                hi.y = pack_hi(h2, h3);
                lo.x = pack_bf16(v.x - __bfloat162float(h0),
                                 v.y - __bfloat162float(h1));
                lo.y = pack_bf16(v.z - __bfloat162float(h2),
                                 v.w - __bfloat162float(h3));
                *(uint2*)(sm + oc * 144 + cg * 8) = hi;
                *(uint2*)(sm + A_TILE_B + oc * 144 + cg * 8) = lo;
            }
            // --- B fill: x[c][pix] fp32 -> transposed [pix][c] bf16 hi/lo ---
            #pragma unroll
            for (int it = 0; it < 8; it++) {
                int t   = it * 256 + tid;
                int cg  = t >> 7;          // 0..15
                int pix = t & 127;
                const float* xp = xb + (size_t)(kt * 64 + cg * 4) * HW + pl0 + pix;
                float v0 = xp[0];
                float v1 = xp[HW];
                float v2 = xp[2 * HW];
                float v3 = xp[3 * HW];
                __nv_bfloat16 h0 = __float2bfloat16(v0);
                __nv_bfloat16 h1 = __float2bfloat16(v1);
                __nv_bfloat16 h2 = __float2bfloat16(v2);
                __nv_bfloat16 h3 = __float2bfloat16(v3);
                uint2 hi, lo;
                hi.x = pack_hi(h0, h1);
                hi.y = pack_hi(h2, h3);
                lo.x = pack_bf16(v0 - __bfloat162float(h0),
                                 v1 - __bfloat162float(h1));
                lo.y = pack_bf16(v2 - __bfloat162float(h2),
                                 v3 - __bfloat162float(h3));
                *(uint2*)(sm + 2 * A_TILE_B + pix * 144 + cg * 8) = hi;
                *(uint2*)(sm + 2 * A_TILE_B + B_TILE_B + pix * 144 + cg * 8) = lo;
            }
            __syncthreads();

            #pragma unroll
            for (int pp = 0; pp < 3; pp++) {
                uint32_t aBase = uS + selA[pp] * A_TILE_B + aLane;
                uint32_t bBase = uS + 2 * A_TILE_B + selB[pp] * B_TILE_B + bLane;
                #pragma unroll
                for (int ks = 0; ks < 4; ks++) {
                    uint32_t af[2][4];
                    uint32_t bf[4][2];
                    #pragma unroll
                    for (int i = 0; i < 2; i++) {
                        uint32_t ad = aBase + i * (16 * 144) + ks * 32;
                        asm volatile(
                            "ldmatrix.sync.aligned.m8n8.x4.shared.b16 "
                            "{%0,%1,%2,%3}, [%4];"
                            : "=r"(af[i][0]), "=r"(af[i][1]),
                              "=r"(af[i][2]), "=r"(af[i][3]) : "r"(ad));
                    }
                    #pragma unroll
                    for (int jp = 0; jp < 2; jp++) {
                        uint32_t bd = bBase + jp * (16 * 144) + ks * 32;
                        asm volatile(
                            "ldmatrix.sync.aligned.m8n8.x4.shared.b16 "
                            "{%0,%1,%2,%3}, [%4];"
                            : "=r"(bf[2 * jp][0]), "=r"(bf[2 * jp][1]),
                              "=r"(bf[2 * jp + 1][0]), "=r"(bf[2 * jp + 1][1])
                            : "r"(bd));
                    }
                    #pragma unroll
                    for (int i = 0; i < 2; i++)
                        #pragma unroll
                        for (int j = 0; j < 4; j++)
                            mma_bf16(acc[i][j], af[i], bf[j]);
                }
            }
        }

        int g  = l >> 2;
        int tc = l & 3;
        #pragma unroll
        for (int i = 0; i < 2; i++) {
            int oc0w = ol + wm * 32 + i * 16 + g;
            #pragma unroll
            for (int j = 0; j < 4; j++) {
                int pix = pl0 + wn * 32 + j * 8 + tc * 2;
                *(float2*)(ob + (size_t)oc0w * HW + pix) =
                    make_float2(acc[i][j][0], acc[i][j][1]);
                *(float2*)(ob + (size_t)(oc0w + 8) * HW + pix) =
                    make_float2(acc[i][j][2], acc[i][j][3]);
            }
        }
    } else {
        // =================== SIMT fp32 PATH (exact) ===================
        float* Xs = (float*)sm;             // [16][128]
        float* Ws = Xs + 16 * 128;          // [16][68] padded
        int tx = tid & 31;                  // pixel group (4 px)
        int ty = tid >> 5;                  // oc group (8 oc)

        float acc[8][4];
        #pragma unroll
        for (int j = 0; j < 8; j++) {
            acc[j][0] = 0.f; acc[j][1] = 0.f; acc[j][2] = 0.f; acc[j][3] = 0.f;
        }

        for (int kc = 0; kc < 256; kc += 16) {
            __syncthreads();
            #pragma unroll
            for (int i = 0; i < 2; i++) {
                int t   = tid + i * 256;
                int row = t >> 5;
                int c4  = (t & 31) << 2;
                *(float4*)(&Xs[row * 128 + c4]) =
                    *(const float4*)(xb + (size_t)(kc + row) * HW + pl0 + c4);
            }
            {
                int oc = tid >> 2;
                int kg = (tid & 3) << 2;
                float4 v4 = *(const float4*)(w + (size_t)(ol + oc) * 256 + kc + kg);
                Ws[(kg + 0) * 68 + oc] = v4.x;
                Ws[(kg + 1) * 68 + oc] = v4.y;
                Ws[(kg + 2) * 68 + oc] = v4.z;
                Ws[(kg + 3) * 68 + oc] = v4.w;
            }
            __syncthreads();

            #pragma unroll
            for (int kk = 0; kk < 16; kk++) {
                float4 xv = *(const float4*)(&Xs[kk * 128 + (tx << 2)]);
                float4 w0 = *(const float4*)(&Ws[kk * 68 + ty * 8]);
                float4 w1 = *(const float4*)(&Ws[kk * 68 + ty * 8 + 4]);
                float wr[8] = {w0.x, w0.y, w0.z, w0.w, w1.x, w1.y, w1.z, w1.w};
                #pragma unroll
                for (int j = 0; j < 8; j++) {
                    acc[j][0] = fmaf(wr[j], xv.x, acc[j][0]);
                    acc[j][1] = fmaf(wr[j], xv.y, acc[j][1]);
                    acc[j][2] = fmaf(wr[j], xv.z, acc[j][2]);
                    acc[j][3] = fmaf(wr[j], xv.w, acc[j][3]);
                }
            }
        }

        #pragma unroll
        for (int j = 0; j < 8; j++) {
            *(float4*)(ob + (size_t)(ol + ty * 8 + j) * HW + pl0 + (tx << 2)) =
                make_float4(acc[j][0], acc[j][1], acc[j][2], acc[j][3]);
        }
    }
}

// ---------------------------------------------------------------------------
// Attention: one launch, 512 blocks x 192 threads, block-uniform bias mode.
// Per tap: FFMA + EX2 + FADD + FFMA (q*log2e hoisted, q*b precomputed).
// ---------------------------------------------------------------------------
template <bool USEH>
__device__ __forceinline__ void attn_compute(
    const float* __restrict__ ks, const float* __restrict__ vs,
    const float* __restrict__ qp, float* __restrict__ op,
    const float* bias, int tid)
{
    const float LOG2E = 1.4426950408889634f;
    #pragma unroll
    for (int it = 0; it < 3; it++) {
        int gg  = tid + it * 192;
        int row = gg / 12;
        int w0  = (gg - row * 12) << 2;

        float4 q4 = *(const float4*)(qp + row * WD + w0);
        float ql[4] = {q4.x * LOG2E, q4.y * LOG2E, q4.z * LOG2E, q4.w * LOG2E};
        float qb[4][7];
        #pragma unroll
        for (int o = 0; o < 4; o++)
            #pragma unroll
            for (int j = 0; j < 7; j++) qb[o][j] = ql[o] * bias[j];

        float ssum[4] = {0.f, 0.f, 0.f, 0.f};
        float avec[4] = {0.f, 0.f, 0.f, 0.f};

        #pragma unroll
        for (int kh = 0; kh < 7; kh++) {
            const float* kr = &ks[(row + kh) * 56 + w0];
            const float* vr = &vs[(row + kh) * 56 + w0];
            float kvv[12], vvv[12];
            {
                float4 t0 = *(const float4*)(kr);
                float4 t1 = *(const float4*)(kr + 4);
                float4 t2 = *(const float4*)(kr + 8);
                kvv[0]=t0.x; kvv[1]=t0.y; kvv[2]=t0.z; kvv[3]=t0.w;
                kvv[4]=t1.x; kvv[5]=t1.y; kvv[6]=t1.z; kvv[7]=t1.w;
                kvv[8]=t2.x; kvv[9]=t2.y; kvv[10]=t2.z; kvv[11]=t2.w;
                float4 u0 = *(const float4*)(vr);
                float4 u1 = *(const float4*)(vr + 4);
                float4 u2 = *(const float4*)(vr + 8);
                vvv[0]=u0.x; vvv[1]=u0.y; vvv[2]=u0.z; vvv[3]=u0.w;
                vvv[4]=u1.x; vvv[5]=u1.y; vvv[6]=u1.z; vvv[7]=u1.w;
                vvv[8]=u2.x; vvv[9]=u2.y; vvv[10]=u2.z; vvv[11]=u2.w;
            }
            #pragma unroll
            for (int kw = 0; kw < 7; kw++) {
                #pragma unroll
                for (int o = 0; o < 4; o++) {
                    int idx = o + kw + 1;
                    float qbb = USEH ? qb[o][kh] : qb[o][kw];
                    float t = fmaf(ql[o], kvv[idx], qbb);
                    float e;
                    asm("ex2.approx.f32 %0, %1;" : "=f"(e) : "f"(t));
                    ssum[o] += e;
                    avec[o] = fmaf(e, vvv[idx], avec[o]);
                }
            }
        }
        float4 rr = make_float4(avec[0] / ssum[0], avec[1] / ssum[1],
                                avec[2] / ssum[2], avec[3] / ssum[3]);
        *(float4*)(op + row * WD + w0) = rr;
    }
}

__global__ __launch_bounds__(192) void attn_kernel(
    const float* __restrict__ rel_h, const float* __restrict__ rel_w,
    float* __restrict__ out)
{
    __shared__ float kvbuf[2 * 3024];
    float* ks = kvbuf;
    float* vs = kvbuf + 3024;

    int plane = blockIdx.x;
    int c = plane & 255;
    bool useH = (c < 128);

    const float* kp = g_k + (size_t)plane * HW;
    const float* vp = g_v + (size_t)plane * HW;
    const float* qp = g_q + (size_t)plane * HW;
    float*       op = out + (size_t)plane * HW;

    int tid = threadIdx.x;

    for (int i = tid; i < 1512; i += 192)
        ((float4*)kvbuf)[i] = make_float4(0.f, 0.f, 0.f, 0.f);
    __syncthreads();
    for (int i = tid; i < 576; i += 192) {
        int y  = i / 12;
        int x4 = (i - y * 12) << 2;
        int s  = (y + 3) * 56 + x4 + 4;
        *(float4*)(ks + s) = *(const float4*)(kp + y * WD + x4);
        *(float4*)(vs + s) = *(const float4*)(vp + y * WD + x4);
    }
    const float* rb = useH ? (rel_h + c * 7) : (rel_w + (c - 128) * 7);
    float bias[7];
    #pragma unroll
    for (int j = 0; j < 7; j++) bias[j] = rb[j];
    __syncthreads();

    if (useH) attn_compute<true >(ks, vs, qp, op, bias, tid);
    else      attn_compute<false>(ks, vs, qp, op, bias, tid);
}

extern "C" void kernel_launch(void* const* d_in, const int* in_sizes, int n_in,
                              void* d_out, int out_size) {
    const float* x  = (const float*)d_in[0];
    const float* wq = (const float*)d_in[1];
    const float* wk = (const float*)d_in[2];
    const float* wv = (const float*)d_in[3];
    const float* rh = (const float*)d_in[4];
    const float* rw = (const float*)d_in[5];

    cudaFuncSetAttribute(gemm_hybrid, cudaFuncAttributeMaxDynamicSharedMemorySize,
                         GEMM_SMEM);

    gemm_hybrid<<<432, 256, GEMM_SMEM>>>(x, wq, wk, wv);
    attn_kernel<<<512, 192>>>(rh, rw, (float*)d_out);
}

// round 7
// speedup vs baseline: 1.3322x; 1.3322x over previous
#include <cuda_runtime.h>
#include <cuda_bf16.h>
#include <cstdint>

#define NB 2
#define NC 256
#define HW 2304   // 48*48
#define WD 48

// ---------------- device scratch ----------------
__device__ float g_q[NB * NC * HW];
__device__ float g_k[NB * NC * HW];
__device__ float g_v[NB * NC * HW];

__device__ __forceinline__ uint32_t smem_u32(const void* p) {
    uint32_t a;
    asm("{ .reg .u64 t; cvta.to.shared.u64 t, %1; cvt.u32.u64 %0, t; }"
        : "=r"(a) : "l"(p));
    return a;
}
__device__ __forceinline__ uint32_t pack_hi(__nv_bfloat16 a, __nv_bfloat16 b) {
    return ((uint32_t)*(uint16_t*)&b << 16) | *(uint16_t*)&a;
}
__device__ __forceinline__ uint32_t pack_bf16(float a, float b) {
    __nv_bfloat162 h = __floats2bfloat162_rn(a, b);
    return *(uint32_t*)&h;
}

// ---------------------------------------------------------------------------
// All-tensor GEMM: D[oc,pix] = sum_c W[oc,c]*X[c,pix], bf16 hi/lo 3-pass
// mma.sync. Tile 64oc x 128pix, K-tile 64, 8 warps, pitch 72 bf16, 3 CTA/SM.
// In-flight fill: reads fp32 x/w from gmem, transpose + bf16 split into smem
// (no prep kernel, no intermediate buffers).
// grid (36 pix-tiles, 12 oc-tiles) = 432 blocks (one wave at 3/SM), 256 thr.
// ---------------------------------------------------------------------------
#define A_TILE_B 9216              // 64 * 144
#define B_TILE_B 18432             // 128 * 144
#define GEMM_SMEM (2 * A_TILE_B + 2 * B_TILE_B)   // 55296

__device__ __forceinline__ void mma_bf16(float* d, const uint32_t* a,
                                         const uint32_t* b) {
    asm volatile(
        "mma.sync.aligned.m16n8k16.row.col.f32.bf16.bf16.f32 "
        "{%0,%1,%2,%3}, {%4,%5,%6,%7}, {%8,%9}, {%0,%1,%2,%3};"
        : "+f"(d[0]), "+f"(d[1]), "+f"(d[2]), "+f"(d[3])
        : "r"(a[0]), "r"(a[1]), "r"(a[2]), "r"(a[3]), "r"(b[0]), "r"(b[1]));
}

__global__ __launch_bounds__(256, 3) void gemm_kernel(
    const float* __restrict__ x, const float* __restrict__ wq,
    const float* __restrict__ wk, const float* __restrict__ wv)
{
    extern __shared__ char sm[];
    uint32_t uS = smem_u32(sm);

    int N0  = blockIdx.x * 128;
    int oc0 = blockIdx.y * 64;
    int which = oc0 >> 8;
    int ol    = oc0 & 255;
    const float* w   = (which == 0) ? wq : (which == 1) ? wk : wv;
    float*      obuf = (which == 0) ? g_q : (which == 1) ? g_k : g_v;

    int b   = N0 / HW;
    int pl0 = N0 - b * HW;
    const float* xb = x + (size_t)b * NC * HW;
    float* ob = obuf + (size_t)b * NC * HW;

    int tid = threadIdx.x;
    int l   = tid & 31;
    int wid = tid >> 5;
    int wm  = wid >> 2;       // 0..1, 32 oc each
    int wn  = wid & 3;        // 0..3, 32 pix each

    float acc[2][4][4];
    #pragma unroll
    for (int i = 0; i < 2; i++)
        #pragma unroll
        for (int j = 0; j < 4; j++)
            #pragma unroll
            for (int q = 0; q < 4; q++) acc[i][j][q] = 0.f;

    uint32_t aLane = (uint32_t)((wm * 32 + (l & 15)) * 144 + (l >> 4) * 16);
    uint32_t bLane = (uint32_t)((wn * 32 + ((l >> 4) & 1) * 8 + (l & 7)) * 144
                                + ((l >> 3) & 1) * 16);
    const int selA[3] = {0, 0, 1};
    const int selB[3] = {0, 1, 0};

    for (int kt = 0; kt < 4; kt++) {
        __syncthreads();
        // --- A fill: W[ol..ol+63][kt*64..+63] fp32 -> bf16 hi/lo ---
        #pragma unroll
        for (int it = 0; it < 4; it++) {
            int t  = it * 256 + tid;
            int oc = t >> 4;
            int cg = t & 15;
            float4 v = *(const float4*)(w + (size_t)(ol + oc) * 256
                                        + kt * 64 + cg * 4);
            __nv_bfloat16 h0 = __float2bfloat16(v.x);
            __nv_bfloat16 h1 = __float2bfloat16(v.y);
            __nv_bfloat16 h2 = __float2bfloat16(v.z);
            __nv_bfloat16 h3 = __float2bfloat16(v.w);
            uint2 hi, lo;
            hi.x = pack_hi(h0, h1);
            hi.y = pack_hi(h2, h3);
            lo.x = pack_bf16(v.x - __bfloat162float(h0),
                             v.y - __bfloat162float(h1));
            lo.y = pack_bf16(v.z - __bfloat162float(h2),
                             v.w - __bfloat162float(h3));
            *(uint2*)(sm + oc * 144 + cg * 8) = hi;
            *(uint2*)(sm + A_TILE_B + oc * 144 + cg * 8) = lo;
        }
        // --- B fill: x[c][pix] -> transposed [pix][c] bf16 hi/lo ---
        #pragma unroll
        for (int it = 0; it < 8; it++) {
            int t   = it * 256 + tid;
            int cg  = t >> 7;
            int pix = t & 127;
            const float* xp = xb + (size_t)(kt * 64 + cg * 4) * HW + pl0 + pix;
            float v0 = xp[0];
            float v1 = xp[HW];
            float v2 = xp[2 * HW];
            float v3 = xp[3 * HW];
            __nv_bfloat16 h0 = __float2bfloat16(v0);
            __nv_bfloat16 h1 = __float2bfloat16(v1);
            __nv_bfloat16 h2 = __float2bfloat16(v2);
            __nv_bfloat16 h3 = __float2bfloat16(v3);
            uint2 hi, lo;
            hi.x = pack_hi(h0, h1);
            hi.y = pack_hi(h2, h3);
            lo.x = pack_bf16(v0 - __bfloat162float(h0),
                             v1 - __bfloat162float(h1));
            lo.y = pack_bf16(v2 - __bfloat162float(h2),
                             v3 - __bfloat162float(h3));
            *(uint2*)(sm + 2 * A_TILE_B + pix * 144 + cg * 8) = hi;
            *(uint2*)(sm + 2 * A_TILE_B + B_TILE_B + pix * 144 + cg * 8) = lo;
        }
        __syncthreads();

        #pragma unroll
        for (int pp = 0; pp < 3; pp++) {
            uint32_t aBase = uS + selA[pp] * A_TILE_B + aLane;
            uint32_t bBase = uS + 2 * A_TILE_B + selB[pp] * B_TILE_B + bLane;
            #pragma unroll
            for (int ks = 0; ks < 4; ks++) {
                uint32_t af[2][4];
                uint32_t bf[4][2];
                #pragma unroll
                for (int i = 0; i < 2; i++) {
                    uint32_t ad = aBase + i * (16 * 144) + ks * 32;
                    asm volatile(
                        "ldmatrix.sync.aligned.m8n8.x4.shared.b16 "
                        "{%0,%1,%2,%3}, [%4];"
                        : "=r"(af[i][0]), "=r"(af[i][1]),
                          "=r"(af[i][2]), "=r"(af[i][3]) : "r"(ad));
                }
                #pragma unroll
                for (int jp = 0; jp < 2; jp++) {
                    uint32_t bd = bBase + jp * (16 * 144) + ks * 32;
                    asm volatile(
                        "ldmatrix.sync.aligned.m8n8.x4.shared.b16 "
                        "{%0,%1,%2,%3}, [%4];"
                        : "=r"(bf[2 * jp][0]), "=r"(bf[2 * jp][1]),
                          "=r"(bf[2 * jp + 1][0]), "=r"(bf[2 * jp + 1][1])
                        : "r"(bd));
                }
                #pragma unroll
                for (int i = 0; i < 2; i++)
                    #pragma unroll
                    for (int j = 0; j < 4; j++)
                        mma_bf16(acc[i][j], af[i], bf[j]);
            }
        }
    }

    int g  = l >> 2;
    int tc = l & 3;
    #pragma unroll
    for (int i = 0; i < 2; i++) {
        int ocw = ol + wm * 32 + i * 16 + g;
        #pragma unroll
        for (int j = 0; j < 4; j++) {
            int pix = pl0 + wn * 32 + j * 8 + tc * 2;
            *(float2*)(ob + (size_t)ocw * HW + pix) =
                make_float2(acc[i][j][0], acc[i][j][1]);
            *(float2*)(ob + (size_t)(ocw + 8) * HW + pix) =
                make_float2(acc[i][j][2], acc[i][j][3]);
        }
    }
}

// ---------------------------------------------------------------------------
// Attention v3: 1024 blocks (plane x half), 288 threads, ONE group (4 px)
// per thread. Half-plane k/v tile (30x56, zero-padded) = 13.4KB smem ->
// 7 blocks/SM, ~63 warps/SM, one wave. Per tap: FFMA + EX2 + FADD + FFMA.
// ---------------------------------------------------------------------------
template <bool USEH>
__device__ __forceinline__ void attn_body(
    const float* __restrict__ ks, const float* __restrict__ vs,
    const float* __restrict__ qrow, float* __restrict__ orow,
    const float* bias, int r, int w0)
{
    const float LOG2E = 1.4426950408889634f;
    float4 q4 = *(const float4*)(qrow + w0);
    float ql[4] = {q4.x * LOG2E, q4.y * LOG2E, q4.z * LOG2E, q4.w * LOG2E};
    float qb[4][7];
    #pragma unroll
    for (int o = 0; o < 4; o++)
        #pragma unroll
        for (int j = 0; j < 7; j++) qb[o][j] = ql[o] * bias[j];

    float ssum[4] = {0.f, 0.f, 0.f, 0.f};
    float avec[4] = {0.f, 0.f, 0.f, 0.f};

    #pragma unroll
    for (int kh = 0; kh < 7; kh++) {
        const float* kr = &ks[(r + kh) * 56 + w0];
        const float* vr = &vs[(r + kh) * 56 + w0];
        float kvv[12], vvv[12];
        {
            float4 t0 = *(const float4*)(kr);
            float4 t1 = *(const float4*)(kr + 4);
            float4 t2 = *(const float4*)(kr + 8);
            kvv[0]=t0.x; kvv[1]=t0.y; kvv[2]=t0.z; kvv[3]=t0.w;
            kvv[4]=t1.x; kvv[5]=t1.y; kvv[6]=t1.z; kvv[7]=t1.w;
            kvv[8]=t2.x; kvv[9]=t2.y; kvv[10]=t2.z; kvv[11]=t2.w;
            float4 u0 = *(const float4*)(vr);
            float4 u1 = *(const float4*)(vr + 4);
            float4 u2 = *(const float4*)(vr + 8);
            vvv[0]=u0.x; vvv[1]=u0.y; vvv[2]=u0.z; vvv[3]=u0.w;
            vvv[4]=u1.x; vvv[5]=u1.y; vvv[6]=u1.z; vvv[7]=u1.w;
            vvv[8]=u2.x; vvv[9]=u2.y; vvv[10]=u2.z; vvv[11]=u2.w;
        }
        #pragma unroll
        for (int kw = 0; kw < 7; kw++) {
            #pragma unroll
            for (int o = 0; o < 4; o++) {
                int idx = o + kw + 1;
                float qbb = USEH ? qb[o][kh] : qb[o][kw];
                float t = fmaf(ql[o], kvv[idx], qbb);
                float e;
                asm("ex2.approx.f32 %0, %1;" : "=f"(e) : "f"(t));
                ssum[o] += e;
                avec[o] = fmaf(e, vvv[idx], avec[o]);
            }
        }
    }
    float4 rr = make_float4(avec[0] / ssum[0], avec[1] / ssum[1],
                            avec[2] / ssum[2], avec[3] / ssum[3]);
    *(float4*)(orow + w0) = rr;
}

__global__ __launch_bounds__(288) void attn_kernel(
    const float* __restrict__ rel_h, const float* __restrict__ rel_w,
    float* __restrict__ out)
{
    __shared__ float kvbuf[2 * 30 * 56];    // 30 rows (24 + halo), pitch 56
    float* ks = kvbuf;
    float* vs = kvbuf + 30 * 56;

    int plane = blockIdx.x >> 1;        // b*256 + c
    int half  = blockIdx.x & 1;
    int y0    = half * 24;
    int ybase = y0 - 3;
    int c = plane & 255;
    bool useH = (c < 128);

    const float* kp = g_k + (size_t)plane * HW;
    const float* vp = g_v + (size_t)plane * HW;
    const float* qp = g_q + (size_t)plane * HW;
    float*       op = out + (size_t)plane * HW;

    int tid = threadIdx.x;

    // clear full tile (840 float4)
    #pragma unroll
    for (int i = tid; i < 840; i += 288)
        ((float4*)kvbuf)[i] = make_float4(0.f, 0.f, 0.f, 0.f);
    __syncthreads();
    // fill valid rows (30 rows x 12 float4 each)
    for (int i = tid; i < 360; i += 288) {
        int r  = i / 12;
        int x4 = (i - r * 12) << 2;
        int gy = ybase + r;
        if ((unsigned)gy < 48u) {
            *(float4*)(ks + r * 56 + x4 + 4) = *(const float4*)(kp + gy * WD + x4);
            *(float4*)(vs + r * 56 + x4 + 4) = *(const float4*)(vp + gy * WD + x4);
        }
    }
    const float* rb = useH ? (rel_h + c * 7) : (rel_w + (c - 128) * 7);
    float bias[7];
    #pragma unroll
    for (int j = 0; j < 7; j++) bias[j] = rb[j];
    __syncthreads();

    int r  = tid / 12;                 // 0..23 local row
    int w0 = (tid - r * 12) << 2;
    int gy = y0 + r;
    const float* qrow = qp + gy * WD;
    float*       orow = op + gy * WD;

    if (useH) attn_body<true >(ks, vs, qrow, orow, bias, r, w0);
    else      attn_body<false>(ks, vs, qrow, orow, bias, r, w0);
}

extern "C" void kernel_launch(void* const* d_in, const int* in_sizes, int n_in,
                              void* d_out, int out_size) {
    const float* x  = (const float*)d_in[0];
    const float* wq = (const float*)d_in[1];
    const float* wk = (const float*)d_in[2];
    const float* wv = (const float*)d_in[3];
    const float* rh = (const float*)d_in[4];
    const float* rw = (const float*)d_in[5];

    cudaFuncSetAttribute(gemm_kernel, cudaFuncAttributeMaxDynamicSharedMemorySize,
                         GEMM_SMEM);

    gemm_kernel<<<dim3(36, 12), 256, GEMM_SMEM>>>(x, wq, wk, wv);
    attn_kernel<<<1024, 288>>>(rh, rw, (float*)d_out);
}